// round 13
// baseline (speedup 1.0000x reference)
#include <cuda_runtime.h>
#include <float.h>

// ROI max pooling, SINGLE kernel. 128 thr x float2; each tile CTA computes
// TWO vertically adjacent 4x4 window-max tiles sequentially (single wave).
// feat: [B=8, H=50, W=50, C=256] fp32 NHWC; rois: [N,5] (img,x1,y1,x2,y2) incl.
// Dataset ROIs are 28x28 with 7x7 pooling -> each bin = aligned 4x4 window at
// (y1+4br, x1+4bc). 4x4 tiles partition the 47x47 window-origin grid; a CTA
// streams input rows, keeps 4x4 window maxes in registers, parks them in
// smem, scans the ROI list for consumers, scatters to out. Twice.
// Extra per-ROI CTAs handle any non-28x28 ROI via the general path.

#define FH 50
#define FW 50
#define CCH 256
#define PH 7
#define PW 7
#define NXC 12                   // tiles per row: ceil(47/4)
#define NYP 6                    // vertical tile PAIRS: 12 tile-rows / 2
#define NTCTA (8 * NYP * NXC)    // 576 tile CTAs
#define MAXM 256                 // match-list capacity per sub-tile

__device__ __forceinline__ float2 fmax2(float2 a, float2 b) {
    float2 r;
    r.x = fmaxf(a.x, b.x);
    r.y = fmaxf(a.y, b.y);
    return r;
}

__global__ __launch_bounds__(128, 8)
void roi_pool_fused(const float* __restrict__ feat,
                    const int*   __restrict__ rois,
                    float*       __restrict__ out,
                    int n_rois)
{
    const int tid  = threadIdx.x;        // 0..127
    const int coff = tid * 2;            // 2 channels per thread

    // ---------- fallback CTAs: one per ROI, only act on non-28x28 ----------
    if (blockIdx.x >= NTCTA) {
        const int roi = blockIdx.x - NTCTA;
        if (roi >= n_rois) return;
        const int* r = rois + roi * 5;
        const int img = r[0], x1 = r[1], y1 = r[2], x2 = r[3], y2 = r[4];
        const int roi_h = y2 - y1 + 1;
        const int roi_w = x2 - x1 + 1;
        if (roi_h == 28 && roi_w == 28) return;   // handled by tile CTAs

        const float* base = feat
            + (((size_t)img * FH + (size_t)y1) * FW + (size_t)x1) * CCH + coff;
        for (int br = 0; br < PH; ++br) {
            const int rs = (br * roi_h + PH - 1) / PH;
            const int re = (br == PH - 1) ? roi_h
                                          : ((br + 1) * roi_h + PH - 1) / PH;
            for (int bc = 0; bc < PW; ++bc) {
                const int cs = (bc * roi_w + PW - 1) / PW;
                const int ce = (bc == PW - 1) ? roi_w
                                              : ((bc + 1) * roi_w + PW - 1) / PW;
                float2 m = make_float2(-FLT_MAX, -FLT_MAX);
                for (int y = rs; y < re; ++y) {
                    const float* rowp = base + (size_t)y * (FW * CCH);
                    for (int x = cs; x < ce; ++x) {
                        const float2 v =
                            *reinterpret_cast<const float2*>(rowp + (size_t)x * CCH);
                        m = fmax2(m, v);
                    }
                }
                *reinterpret_cast<float2*>(
                    out + ((size_t)((roi * PH + br) * PW + bc)) * CCH + coff) = m;
            }
        }
        return;
    }

    // ---------------------- tile CTAs ----------------------
    __shared__ float2 s_vm[16][128];     // one sub-tile's 4x4 maxes, 16 KB
    __shared__ int    s_roi[MAXM];
    __shared__ int    s_pk[MAXM];        // packed br|bc|yloc|xloc
    __shared__ int    s_cnt;

    const int id = blockIdx.x;           // ((b*NYP)+typ)*NXC + tx
    const int tx  = id % NXC;
    const int t1  = id / NXC;
    const int typ = t1 % NYP;
    const int b   = t1 / NYP;
    const int x0  = tx * 4;

    if (tid == 0) s_cnt = 0;

    const float2 NEG = make_float2(-FLT_MAX, -FLT_MAX);

    for (int sub = 0; sub < 2; ++sub) {
        const int y0 = (typ * 2 + sub) * 4;

        // Streaming: per input row j, 7 loads -> 4 horizontal window maxes ->
        // update vertical accumulators of output rows r in [j-3, j] & [0,3].
        float2 acc[4][4];
        #pragma unroll
        for (int r = 0; r < 4; ++r)
            #pragma unroll
            for (int c = 0; c < 4; ++c)
                acc[r][c] = NEG;

        #pragma unroll
        for (int j = 0; j < 7; ++j) {
            const int y = y0 + j;
            float2 v[7];
            if (y < FH) {
                const float* rowp =
                    feat + ((size_t)(b * FH + y) * FW) * CCH + coff;
                #pragma unroll
                for (int k = 0; k < 7; ++k) {
                    const int x = x0 + k;
                    v[k] = (x < FW)
                         ? *reinterpret_cast<const float2*>(rowp + (size_t)x * CCH)
                         : NEG;
                }
            } else {
                #pragma unroll
                for (int k = 0; k < 7; ++k) v[k] = NEG;
            }
            const float2 m01 = fmax2(v[0], v[1]);
            const float2 m12 = fmax2(v[1], v[2]);
            const float2 m23 = fmax2(v[2], v[3]);
            const float2 m34 = fmax2(v[3], v[4]);
            const float2 m45 = fmax2(v[4], v[5]);
            const float2 m56 = fmax2(v[5], v[6]);
            float2 h[4];
            h[0] = fmax2(m01, m23);
            h[1] = fmax2(m12, m34);
            h[2] = fmax2(m23, m45);
            h[3] = fmax2(m34, m56);

            #pragma unroll
            for (int r = 0; r < 4; ++r)
                if (j >= r && j <= r + 3)
                    #pragma unroll
                    for (int c = 0; c < 4; ++c)
                        acc[r][c] = fmax2(acc[r][c], h[c]);
        }

        // Park finished sub-tile in smem for dynamically-indexed scatter.
        #pragma unroll
        for (int r = 0; r < 4; ++r)
            #pragma unroll
            for (int c = 0; c < 4; ++c)
                s_vm[r * 4 + c][tid] = acc[r][c];

        __syncthreads();   // park + s_cnt reset visible before scan

        // Scan ROIs; each thread handles rois tid, tid+128, ...
        for (int roi = tid; roi < n_rois; roi += 128) {
            const int* r = rois + roi * 5;
            const int img = r[0], x1 = r[1], y1 = r[2], x2 = r[3], y2 = r[4];
            if (img != b) continue;
            if (y2 - y1 != 27 || x2 - x1 != 27) continue; // fallback handles
            const int dy = y0 - y1;
            const int dx = x0 - x1;
            if (dy < -3 || dy > 24 || dx < -3 || dx > 24) continue;
            const int br = (dy + 3) >> 2;    // unique bin row in this tile
            const int bc = (dx + 3) >> 2;
            const int yloc = 4 * br - dy;    // 0..3
            const int xloc = 4 * bc - dx;    // 0..3
            const int slot = atomicAdd(&s_cnt, 1);
            if (slot < MAXM) {
                s_roi[slot] = roi;
                s_pk[slot]  = (br << 12) | (bc << 8) | (yloc << 4) | xloc;
            }
        }

        __syncthreads();

        // Scatter: every thread writes its 2 channels for each match.
        const int cnt = min(s_cnt, MAXM);
        for (int i = 0; i < cnt; ++i) {
            const int roi = s_roi[i];
            const int pk  = s_pk[i];
            const int br   = (pk >> 12) & 0xF;
            const int bc   = (pk >> 8)  & 0xF;
            const int yloc = (pk >> 4)  & 0xF;
            const int xloc =  pk        & 0xF;
            *reinterpret_cast<float2*>(
                out + ((size_t)((roi * PH + br) * PW + bc)) * CCH + coff)
                = s_vm[yloc * 4 + xloc][tid];
        }

        __syncthreads();   // done reading s_vm/s_roi before next sub-tile
        if (sub == 0 && tid == 0) s_cnt = 0;
    }
}

extern "C" void kernel_launch(void* const* d_in, const int* in_sizes, int n_in,
                              void* d_out, int out_size)
{
    const float* feat = (const float*)d_in[0];
    const int*   rois = (const int*)d_in[1];
    const int n_rois = in_sizes[1] / 5;
    float* out = (float*)d_out;

    roi_pool_fused<<<NTCTA + n_rois, 128>>>(feat, rois, out, n_rois);
}

// round 14
// speedup vs baseline: 1.1905x; 1.1905x over previous
#include <cuda_runtime.h>
#include <float.h>

// ROI max pooling, SINGLE kernel, single wave (1152 CTAs = 8/SM x 144 SMs).
// feat: [B=8, H=50, W=50, C=256] fp32 NHWC; rois: [N,5] (img,x1,y1,x2,y2) incl.
// Dataset ROIs are 28x28 with 7x7 pooling -> each bin = aligned 4x4 window at
// (y1+4br, x1+4bc). 4x4 tiles partition the 47x47 window-origin grid; each
// tile CTA scans the ROI list for consumers, streams 7 input rows (direct
// LDG, float2/thread), keeps the 4x4 window maxes in registers, parks them
// in smem, scatters to out. Non-28x28 ROIs are handled by the same CTAs via
// a strided general path (CTA-uniform branch, no-op on this dataset).

#define FH 50
#define FW 50
#define CCH 256
#define PH 7
#define PW 7
#define NXC 12                   // tiles per row: ceil(47/4)
#define NYC 12
#define NTILES (8 * NYC * NXC)   // 1152
#define MAXM 256                 // match-list capacity per tile

__device__ __forceinline__ float2 fmax2(float2 a, float2 b) {
    float2 r;
    r.x = fmaxf(a.x, b.x);
    r.y = fmaxf(a.y, b.y);
    return r;
}

__global__ __launch_bounds__(128, 8)
void roi_pool_fused(const float* __restrict__ feat,
                    const int*   __restrict__ rois,
                    float*       __restrict__ out,
                    int n_rois)
{
    const int tid  = threadIdx.x;        // 0..127
    const int coff = tid * 2;            // 2 channels per thread

    __shared__ float2 s_vm[16][128];     // finished 4x4 window maxes, 16 KB
    __shared__ int    s_roi[MAXM];
    __shared__ int    s_pk[MAXM];        // packed br|bc|yloc|xloc
    __shared__ int    s_cnt;

    const int id = blockIdx.x;           // ((b*NYC)+ty)*NXC + tx
    const int tx = id % NXC;
    const int t1 = id / NXC;
    const int ty = t1 % NYC;
    const int b  = t1 / NYC;
    const int x0 = tx * 4;
    const int y0 = ty * 4;

    if (tid == 0) s_cnt = 0;
    __syncthreads();                     // s_cnt=0 visible before atomics

    // ---- Scan ROIs first (overlaps with subsequent load issue) ----
    for (int roi = tid; roi < n_rois; roi += 128) {
        const int* r = rois + roi * 5;
        const int img = r[0], x1 = r[1], y1 = r[2], x2 = r[3], y2 = r[4];
        if (img != b) continue;
        if (y2 - y1 != 27 || x2 - x1 != 27) continue;  // general path below
        const int dy = y0 - y1;
        const int dx = x0 - x1;
        if (dy < -3 || dy > 24 || dx < -3 || dx > 24) continue;
        const int br = (dy + 3) >> 2;      // unique bin row landing in tile
        const int bc = (dx + 3) >> 2;
        const int yloc = 4 * br - dy;      // 0..3
        const int xloc = 4 * bc - dx;      // 0..3
        const int slot = atomicAdd(&s_cnt, 1);
        if (slot < MAXM) {
            s_roi[slot] = roi;
            s_pk[slot]  = (br << 12) | (bc << 8) | (yloc << 4) | xloc;
        }
    }

    // ---- Streaming 4x4 window max (32-bit addressing in hot path) ----
    const float2 NEG = make_float2(-FLT_MAX, -FLT_MAX);
    float2 acc[4][4];
    #pragma unroll
    for (int r = 0; r < 4; ++r)
        #pragma unroll
        for (int c = 0; c < 4; ++c)
            acc[r][c] = NEG;

    // base for (b, y0, x0, coff); all element offsets < 2^31
    const float* tbase = feat
        + (unsigned)(((b * FH + y0) * FW + x0) * CCH + coff);

    #pragma unroll
    for (int j = 0; j < 7; ++j) {
        const int y = y0 + j;
        float2 v[7];
        if (y < FH) {
            const float* rowp = tbase + (unsigned)(j * FW * CCH);
            #pragma unroll
            for (int k = 0; k < 7; ++k) {
                v[k] = (x0 + k < FW)
                     ? *reinterpret_cast<const float2*>(rowp + (unsigned)(k * CCH))
                     : NEG;
            }
        } else {
            #pragma unroll
            for (int k = 0; k < 7; ++k) v[k] = NEG;
        }
        const float2 m01 = fmax2(v[0], v[1]);
        const float2 m12 = fmax2(v[1], v[2]);
        const float2 m23 = fmax2(v[2], v[3]);
        const float2 m34 = fmax2(v[3], v[4]);
        const float2 m45 = fmax2(v[4], v[5]);
        const float2 m56 = fmax2(v[5], v[6]);
        float2 h[4];
        h[0] = fmax2(m01, m23);
        h[1] = fmax2(m12, m34);
        h[2] = fmax2(m23, m45);
        h[3] = fmax2(m34, m56);

        #pragma unroll
        for (int r = 0; r < 4; ++r)
            if (j >= r && j <= r + 3)
                #pragma unroll
                for (int c = 0; c < 4; ++c)
                    acc[r][c] = fmax2(acc[r][c], h[c]);
    }

    // Park finished tile in smem for dynamically-indexed scatter reads.
    #pragma unroll
    for (int r = 0; r < 4; ++r)
        #pragma unroll
        for (int c = 0; c < 4; ++c)
            s_vm[r * 4 + c][tid] = acc[r][c];

    __syncthreads();   // park + match list visible

    // ---- Scatter: every thread writes its 2 channels per match ----
    const int cnt = min(s_cnt, MAXM);
    for (int i = 0; i < cnt; ++i) {
        const int roi = s_roi[i];
        const int pk  = s_pk[i];
        const int br   = (pk >> 12) & 0xF;
        const int bc   = (pk >> 8)  & 0xF;
        const int yloc = (pk >> 4)  & 0xF;
        const int xloc =  pk        & 0xF;
        *reinterpret_cast<float2*>(
            out + (unsigned)(((roi * PH + br) * PW + bc) * CCH + coff))
            = s_vm[yloc * 4 + xloc][tid];
    }

    // ---- General path for non-28x28 ROIs, folded into tile CTAs ----
    // CTA-uniform branch per ROI; no-op when all ROIs are 28x28.
    for (int roi = blockIdx.x; roi < n_rois; roi += NTILES) {
        const int* r = rois + roi * 5;
        const int img = r[0], x1 = r[1], y1 = r[2], x2 = r[3], y2 = r[4];
        const int roi_h = y2 - y1 + 1;
        const int roi_w = x2 - x1 + 1;
        if (roi_h == 28 && roi_w == 28) continue;   // handled above

        const float* base = feat
            + (((size_t)img * FH + (size_t)y1) * FW + (size_t)x1) * CCH + coff;
        for (int br = 0; br < PH; ++br) {
            const int rs = (br * roi_h + PH - 1) / PH;
            const int re = (br == PH - 1) ? roi_h
                                          : ((br + 1) * roi_h + PH - 1) / PH;
            for (int bc = 0; bc < PW; ++bc) {
                const int cs = (bc * roi_w + PW - 1) / PW;
                const int ce = (bc == PW - 1) ? roi_w
                                              : ((bc + 1) * roi_w + PW - 1) / PW;
                float2 m = make_float2(-FLT_MAX, -FLT_MAX);
                for (int y = rs; y < re; ++y) {
                    const float* rowp = base + (size_t)y * (FW * CCH);
                    for (int x = cs; x < ce; ++x) {
                        const float2 v =
                            *reinterpret_cast<const float2*>(rowp + (size_t)x * CCH);
                        m = fmax2(m, v);
                    }
                }
                *reinterpret_cast<float2*>(
                    out + ((size_t)((roi * PH + br) * PW + bc)) * CCH + coff) = m;
            }
        }
    }
}

extern "C" void kernel_launch(void* const* d_in, const int* in_sizes, int n_in,
                              void* d_out, int out_size)
{
    const float* feat = (const float*)d_in[0];
    const int*   rois = (const int*)d_in[1];
    const int n_rois = in_sizes[1] / 5;
    float* out = (float*)d_out;

    roi_pool_fused<<<NTILES, 128>>>(feat, rois, out, n_rois);
}